// round 4
// baseline (speedup 1.0000x reference)
#include <cuda_runtime.h>
#include <math.h>

#define BB 128
#define TT 256
#define HH 512
#define G4 2048  // 4*H

// ---------------- scratch (static device memory; no allocations) -------------
// xproj: 2 direction buffers, each [B*T, 4H] fp32 (reused layer0 -> layer1)
__device__ float g_xproj[134217728];   // 2 * 32768 * 2048   (512 MB)
// layer-0 hidden history per direction: [B, T, H] fp32
__device__ float g_hist[33554432];     // 2 * 128*256*512    (128 MB)
// cell state per (layer, dir): [B, H]
__device__ float g_c[262144];          // 4 * 128*512        (1 MB)

// ---------------- tf32 helpers ----------------------------------------------
__device__ __forceinline__ unsigned f2tf32(float f) {
    unsigned r;
    asm("cvt.rna.tf32.f32 %0, %1;" : "=r"(r) : "f"(f));
    return r;
}

__device__ __forceinline__ void mma_tf32(float* c, const unsigned* a, const unsigned* b) {
    asm volatile(
        "mma.sync.aligned.m16n8k8.row.col.f32.tf32.tf32.f32 "
        "{%0,%1,%2,%3}, {%4,%5,%6,%7}, {%8,%9}, {%0,%1,%2,%3};"
        : "+f"(c[0]), "+f"(c[1]), "+f"(c[2]), "+f"(c[3])
        : "r"(a[0]), "r"(a[1]), "r"(a[2]), "r"(a[3]),
          "r"(b[0]), "r"(b[1]));
}

// ---------------- big GEMM: C[M,2048] = A[M,512] @ W[512,2048] + bias --------
// CTA tile 128x128, kc=32, 8 warps as 2(m) x 4(n), warp tile 64x32.
__global__ __launch_bounds__(256)
void gemm_bias_tf32(const float* __restrict__ A,
                    const float* __restrict__ W,
                    const float* __restrict__ bias,
                    float* __restrict__ C)
{
    __shared__ unsigned As[32][132];   // [k][row]
    __shared__ unsigned Bs[32][132];   // [k][col]

    const int tid  = threadIdx.x;
    const int w    = tid >> 5;
    const int lane = tid & 31;
    const int g    = lane >> 2;
    const int tig  = lane & 3;
    const int wm   = w >> 2;           // 0..1
    const int wn   = w & 3;            // 0..3
    const long m0  = (long)blockIdx.y * 128;
    const int  n0  = blockIdx.x * 128;

    float acc[4][4][4];
#pragma unroll
    for (int i = 0; i < 4; i++)
#pragma unroll
        for (int j = 0; j < 4; j++)
#pragma unroll
            for (int q = 0; q < 4; q++) acc[i][j][q] = 0.f;

    for (int kk = 0; kk < 512; kk += 32) {
        // load A tile: 128 rows x 32 k = 1024 float4
#pragma unroll
        for (int i = 0; i < 4; i++) {
            int lin = tid + i * 256;
            int r = lin >> 3, kq = lin & 7;
            float4 v = *(const float4*)(A + (m0 + r) * 512 + kk + kq * 4);
            As[kq * 4 + 0][r] = f2tf32(v.x);
            As[kq * 4 + 1][r] = f2tf32(v.y);
            As[kq * 4 + 2][r] = f2tf32(v.z);
            As[kq * 4 + 3][r] = f2tf32(v.w);
        }
        // load B tile: 32 k x 128 cols = 1024 float4
#pragma unroll
        for (int i = 0; i < 4; i++) {
            int lq = tid + i * 256;
            int k = lq >> 5, cq = lq & 31;
            float4 v = *(const float4*)(W + (size_t)(kk + k) * 2048 + n0 + cq * 4);
            Bs[k][cq * 4 + 0] = f2tf32(v.x);
            Bs[k][cq * 4 + 1] = f2tf32(v.y);
            Bs[k][cq * 4 + 2] = f2tf32(v.z);
            Bs[k][cq * 4 + 3] = f2tf32(v.w);
        }
        __syncthreads();

#pragma unroll
        for (int ks = 0; ks < 4; ks++) {
            const int k0 = ks * 8;
            unsigned a[4][4], bf[4][2];
#pragma unroll
            for (int mt = 0; mt < 4; mt++) {
                int r = wm * 64 + mt * 16;
                a[mt][0] = As[k0 + tig][r + g];
                a[mt][1] = As[k0 + tig][r + g + 8];
                a[mt][2] = As[k0 + tig + 4][r + g];
                a[mt][3] = As[k0 + tig + 4][r + g + 8];
            }
#pragma unroll
            for (int nt = 0; nt < 4; nt++) {
                int cc = wn * 32 + nt * 8 + g;
                bf[nt][0] = Bs[k0 + tig][cc];
                bf[nt][1] = Bs[k0 + tig + 4][cc];
            }
#pragma unroll
            for (int mt = 0; mt < 4; mt++)
#pragma unroll
                for (int nt = 0; nt < 4; nt++)
                    mma_tf32(acc[mt][nt], a[mt], bf[nt]);
        }
        __syncthreads();
    }

    // epilogue: + bias, write fp32
#pragma unroll
    for (int mt = 0; mt < 4; mt++) {
#pragma unroll
        for (int nt = 0; nt < 4; nt++) {
            long r0 = m0 + wm * 64 + mt * 16 + g;
            int cc = n0 + wn * 32 + nt * 8 + tig * 2;
            float b0 = bias[cc], b1 = bias[cc + 1];
            C[r0 * 2048 + cc]           = acc[mt][nt][0] + b0;
            C[r0 * 2048 + cc + 1]       = acc[mt][nt][1] + b1;
            C[(r0 + 8) * 2048 + cc]     = acc[mt][nt][2] + b0;
            C[(r0 + 8) * 2048 + cc + 1] = acc[mt][nt][3] + b1;
        }
    }
}

// ---------------- recurrent step --------------------------------------------
struct StepP {
    const float* xproj;   // [B*T, 2048]
    const float* Wh;      // [512, 2048]
    const float* hprev;   // elem (b,j) at hprev + b*hp_stride + j (unused if first)
    float*       hout;    // elem (b,j) at hout  + b*ho_stride + j
    float*       c;       // [B, 512]
    long hp_stride;
    long ho_stride;
    int  t;
    int  first;
};

// One launch per (layer, step); gridDim = (32 hidden-tiles, 2 directions).
// Each CTA: hidden units [j0, j0+16), C tile 128(batch) x 64 (4 gate groups x 16).
// 8 warps stacked along M (16 rows each), every warp spans all 64 N columns, so
// each thread owns i,f,g,o of its (b,j) pairs in registers.
__global__ __launch_bounds__(256)
void lstm_step(StepP pa, StepP pb)
{
    StepP p = blockIdx.y ? pb : pa;

    __shared__ unsigned As[32][132];  // [k][row(batch)]
    __shared__ unsigned Bs[32][68];   // [k][col(gate-tile)]

    const int tid  = threadIdx.x;
    const int w    = tid >> 5;
    const int lane = tid & 31;
    const int g    = lane >> 2;
    const int tig  = lane & 3;
    const int j0   = blockIdx.x * 16;
    const int mbase = w * 16;

    float acc[8][4];
#pragma unroll
    for (int i = 0; i < 8; i++)
#pragma unroll
        for (int q = 0; q < 4; q++) acc[i][q] = 0.f;

    if (!p.first) {
        for (int kk = 0; kk < 512; kk += 32) {
            // A: h_prev tile 128 rows x 32 k = 1024 float4
#pragma unroll
            for (int i = 0; i < 4; i++) {
                int lin = tid + i * 256;
                int r = lin >> 3, kq = lin & 7;
                float4 v = *(const float4*)(p.hprev + (long)r * p.hp_stride + kk + kq * 4);
                As[kq * 4 + 0][r] = f2tf32(v.x);
                As[kq * 4 + 1][r] = f2tf32(v.y);
                As[kq * 4 + 2][r] = f2tf32(v.z);
                As[kq * 4 + 3][r] = f2tf32(v.w);
            }
            // B: gathered Wh columns {gate*512 + j0 + jj}, 32 k x 64 c = 512 float4
#pragma unroll
            for (int i = 0; i < 2; i++) {
                int lq = tid + i * 256;
                int k = lq >> 4, cq = lq & 15;
                int c = cq * 4;
                int gate = c >> 4;
                int jj = c & 15;
                float4 v = *(const float4*)(p.Wh + (size_t)(kk + k) * 2048 + gate * 512 + j0 + jj);
                Bs[k][c + 0] = f2tf32(v.x);
                Bs[k][c + 1] = f2tf32(v.y);
                Bs[k][c + 2] = f2tf32(v.z);
                Bs[k][c + 3] = f2tf32(v.w);
            }
            __syncthreads();

#pragma unroll
            for (int ks = 0; ks < 4; ks++) {
                const int k0 = ks * 8;
                unsigned a[4];
                a[0] = As[k0 + tig][mbase + g];
                a[1] = As[k0 + tig][mbase + g + 8];
                a[2] = As[k0 + tig + 4][mbase + g];
                a[3] = As[k0 + tig + 4][mbase + g + 8];
#pragma unroll
                for (int nt = 0; nt < 8; nt++) {
                    unsigned b2[2];
                    b2[0] = Bs[k0 + tig][nt * 8 + g];
                    b2[1] = Bs[k0 + tig + 4][nt * 8 + g];
                    mma_tf32(acc[nt], a, b2);
                }
            }
            __syncthreads();
        }
    }

    // ---- epilogue: gates = acc + xproj[t], LSTM cell update, write h --------
#pragma unroll
    for (int rr = 0; rr < 2; rr++) {
        int b = mbase + g + rr * 8;                     // batch row
        size_t xbase = ((size_t)b * TT + p.t) * 2048;
#pragma unroll
        for (int cg = 0; cg < 2; cg++) {
#pragma unroll
            for (int pp = 0; pp < 2; pp++) {
                int q = rr * 2 + pp;                    // C-fragment register index
                int j = j0 + cg * 8 + tig * 2 + pp;     // hidden unit
                float gi = acc[0 + cg][q] + p.xproj[xbase + 0 * 512 + j];
                float gf = acc[2 + cg][q] + p.xproj[xbase + 1 * 512 + j];
                float gg = acc[4 + cg][q] + p.xproj[xbase + 2 * 512 + j];
                float go = acc[6 + cg][q] + p.xproj[xbase + 3 * 512 + j];
                float i_ = 1.f / (1.f + expf(-gi));
                float f_ = 1.f / (1.f + expf(-gf));
                float G_ = tanhf(gg);
                float o_ = 1.f / (1.f + expf(-go));
                float cold = p.first ? 0.f : p.c[b * 512 + j];
                float cn = f_ * cold + i_ * G_;
                p.c[b * 512 + j] = cn;
                p.hout[(long)b * p.ho_stride + j] = o_ * tanhf(cn);
            }
        }
    }
}

// ---------------- host orchestration ----------------------------------------
extern "C" void kernel_launch(void* const* d_in, const int* in_sizes, int n_in,
                              void* d_out, int out_size)
{
    const float* x  = (const float*)d_in[0];   // [128,256,512]
    const float* Wx = (const float*)d_in[1];   // [2,2,512,2048]
    const float* Wh = (const float*)d_in[2];   // [2,2,512,2048]
    const float* bs = (const float*)d_in[3];   // [2,2,2048]
    float* out = (float*)d_out;                // [128,256,1024]

    float *xp_base, *hist_base, *c_base;
    cudaGetSymbolAddress((void**)&xp_base,   g_xproj);
    cudaGetSymbolAddress((void**)&hist_base, g_hist);
    cudaGetSymbolAddress((void**)&c_base,    g_c);

    float* xp[2]   = { xp_base,   xp_base   + (size_t)BB * TT * G4 };
    float* hist[2] = { hist_base, hist_base + (size_t)BB * TT * HH };

    const size_t WSTRIDE = (size_t)HH * G4;    // per (l,d) weight matrix
    const dim3 ggrid(16, 256);                 // 2048/128 x 32768/128

    // ---- layer 0 input projections (both directions) ----
    for (int d = 0; d < 2; d++)
        gemm_bias_tf32<<<ggrid, 256>>>(x, Wx + (size_t)d * WSTRIDE,
                                       bs + d * G4, xp[d]);

    // ---- layer 0 recurrence ----
    for (int s = 0; s < TT; s++) {
        StepP p0, p1;
        // forward (t = s)
        p0.xproj = xp[0];
        p0.Wh = Wh + (size_t)0 * WSTRIDE;
        p0.t = s; p0.first = (s == 0);
        p0.hprev = hist[0] + (size_t)(s > 0 ? s - 1 : 0) * HH;
        p0.hp_stride = (long)TT * HH;
        p0.hout = hist[0] + (size_t)s * HH;
        p0.ho_stride = (long)TT * HH;
        p0.c = c_base + 0 * BB * HH;
        // backward (t = T-1-s)
        int t = TT - 1 - s;
        p1.xproj = xp[1];
        p1.Wh = Wh + (size_t)1 * WSTRIDE;
        p1.t = t; p1.first = (s == 0);
        p1.hprev = hist[1] + (size_t)(s > 0 ? t + 1 : 0) * HH;
        p1.hp_stride = (long)TT * HH;
        p1.hout = hist[1] + (size_t)t * HH;
        p1.ho_stride = (long)TT * HH;
        p1.c = c_base + 1 * BB * HH;
        lstm_step<<<dim3(32, 2), 256>>>(p0, p1);
    }

    // ---- layer 1 input projections from layer-0 hidden history ----
    for (int d = 0; d < 2; d++)
        gemm_bias_tf32<<<ggrid, 256>>>(hist[d], Wx + (size_t)(2 + d) * WSTRIDE,
                                       bs + (2 + d) * G4, xp[d]);

    // ---- layer 1 recurrence (h lives directly in d_out) ----
    for (int s = 0; s < TT; s++) {
        StepP p0, p1;
        // forward: out[b][t][0:512]
        p0.xproj = xp[0];
        p0.Wh = Wh + (size_t)2 * WSTRIDE;
        p0.t = s; p0.first = (s == 0);
        p0.hprev = out + (size_t)(s > 0 ? s - 1 : 0) * 1024;
        p0.hp_stride = (long)TT * 1024;
        p0.hout = out + (size_t)s * 1024;
        p0.ho_stride = (long)TT * 1024;
        p0.c = c_base + 2 * BB * HH;
        // backward: out[b][t][512:1024]
        int t = TT - 1 - s;
        p1.xproj = xp[1];
        p1.Wh = Wh + (size_t)3 * WSTRIDE;
        p1.t = t; p1.first = (s == 0);
        p1.hprev = out + (size_t)(s > 0 ? t + 1 : 0) * 1024 + 512;
        p1.hp_stride = (long)TT * 1024;
        p1.hout = out + (size_t)t * 1024 + 512;
        p1.ho_stride = (long)TT * 1024;
        p1.c = c_base + 3 * BB * HH;
        lstm_step<<<dim3(32, 2), 256>>>(p0, p1);
    }
}

// round 5
// speedup vs baseline: 1.0118x; 1.0118x over previous
#include <cuda_runtime.h>
#include <math.h>

#define BB 128
#define TT 256
#define HH 512
#define G4 2048  // 4*H

// ---------------- scratch (static device memory; no allocations) -------------
__device__ float g_xproj[134217728];   // 2 dirs * 32768 * 2048 fp32 (512 MB)
__device__ float g_hist[33554432];     // 2 dirs * 128*256*512 fp32 (128 MB)

// grid-barrier state (self-cleaning: cnt returns to 0, flag compared relatively)
__device__ unsigned g_barcnt[2];
__device__ unsigned g_barflag[2];

// ---------------- tf32 helpers ----------------------------------------------
__device__ __forceinline__ unsigned f2tf32(float f) {
    unsigned r;
    asm("cvt.rna.tf32.f32 %0, %1;" : "=r"(r) : "f"(f));
    return r;
}

__device__ __forceinline__ void mma_tf32(float* c, const unsigned* a, const unsigned* b) {
    asm volatile(
        "mma.sync.aligned.m16n8k8.row.col.f32.tf32.tf32.f32 "
        "{%0,%1,%2,%3}, {%4,%5,%6,%7}, {%8,%9}, {%0,%1,%2,%3};"
        : "+f"(c[0]), "+f"(c[1]), "+f"(c[2]), "+f"(c[3])
        : "r"(a[0]), "r"(a[1]), "r"(a[2]), "r"(a[3]),
          "r"(b[0]), "r"(b[1]));
}

// ---------------- big GEMM: C[M,2048] = A[M,512] @ W[512,2048] + bias --------
// (unchanged from passing R3 kernel; optimize next round with profile data)
__global__ __launch_bounds__(256)
void gemm_bias_tf32(const float* __restrict__ A,
                    const float* __restrict__ W,
                    const float* __restrict__ bias,
                    float* __restrict__ C)
{
    __shared__ unsigned As[32][132];
    __shared__ unsigned Bs[32][132];

    const int tid  = threadIdx.x;
    const int w    = tid >> 5;
    const int lane = tid & 31;
    const int g    = lane >> 2;
    const int tig  = lane & 3;
    const int wm   = w >> 2;
    const int wn   = w & 3;
    const long m0  = (long)blockIdx.y * 128;
    const int  n0  = blockIdx.x * 128;

    float acc[4][4][4];
#pragma unroll
    for (int i = 0; i < 4; i++)
#pragma unroll
        for (int j = 0; j < 4; j++)
#pragma unroll
            for (int q = 0; q < 4; q++) acc[i][j][q] = 0.f;

    for (int kk = 0; kk < 512; kk += 32) {
#pragma unroll
        for (int i = 0; i < 4; i++) {
            int lin = tid + i * 256;
            int r = lin >> 3, kq = lin & 7;
            float4 v = *(const float4*)(A + (m0 + r) * 512 + kk + kq * 4);
            As[kq * 4 + 0][r] = f2tf32(v.x);
            As[kq * 4 + 1][r] = f2tf32(v.y);
            As[kq * 4 + 2][r] = f2tf32(v.z);
            As[kq * 4 + 3][r] = f2tf32(v.w);
        }
#pragma unroll
        for (int i = 0; i < 4; i++) {
            int lq = tid + i * 256;
            int k = lq >> 5, cq = lq & 31;
            float4 v = *(const float4*)(W + (size_t)(kk + k) * 2048 + n0 + cq * 4);
            Bs[k][cq * 4 + 0] = f2tf32(v.x);
            Bs[k][cq * 4 + 1] = f2tf32(v.y);
            Bs[k][cq * 4 + 2] = f2tf32(v.z);
            Bs[k][cq * 4 + 3] = f2tf32(v.w);
        }
        __syncthreads();

#pragma unroll
        for (int ks = 0; ks < 4; ks++) {
            const int k0 = ks * 8;
            unsigned a[4][4], bf[4][2];
#pragma unroll
            for (int mt = 0; mt < 4; mt++) {
                int r = wm * 64 + mt * 16;
                a[mt][0] = As[k0 + tig][r + g];
                a[mt][1] = As[k0 + tig][r + g + 8];
                a[mt][2] = As[k0 + tig + 4][r + g];
                a[mt][3] = As[k0 + tig + 4][r + g + 8];
            }
#pragma unroll
            for (int nt = 0; nt < 4; nt++) {
                int cc = wn * 32 + nt * 8 + g;
                bf[nt][0] = Bs[k0 + tig][cc];
                bf[nt][1] = Bs[k0 + tig + 4][cc];
            }
#pragma unroll
            for (int mt = 0; mt < 4; mt++)
#pragma unroll
                for (int nt = 0; nt < 4; nt++)
                    mma_tf32(acc[mt][nt], a[mt], bf[nt]);
        }
        __syncthreads();
    }

#pragma unroll
    for (int mt = 0; mt < 4; mt++) {
#pragma unroll
        for (int nt = 0; nt < 4; nt++) {
            long r0 = m0 + wm * 64 + mt * 16 + g;
            int cc = n0 + wn * 32 + nt * 8 + tig * 2;
            float b0 = bias[cc], b1 = bias[cc + 1];
            C[r0 * 2048 + cc]           = acc[mt][nt][0] + b0;
            C[r0 * 2048 + cc + 1]       = acc[mt][nt][1] + b1;
            C[(r0 + 8) * 2048 + cc]     = acc[mt][nt][2] + b0;
            C[(r0 + 8) * 2048 + cc + 1] = acc[mt][nt][3] + b1;
        }
    }
}

// ---------------- persistent recurrence kernel -------------------------------
// One launch per layer. grid = (32 j-tiles, 2 directions), 256 threads.
// Wh tile (512 x 64 gathered gate columns) resident in smem for all 256 steps;
// cell state in registers; h_prev streamed with double buffering; per-direction
// grid barrier between timesteps.
struct RecP {
    const float* xp[2];   // per dir: [B*T, 2048] input projections
    const float* Wh[2];   // per dir: [512, 2048]
    float*       h[2];    // per dir: element (b,t,j) at h + b*bstride + t*tstride + j
    long bstride;
    long tstride;
};

#define WH_STRIDE 72      // padded smem row stride (words) for Wh: banks 8*tig+g -> conflict-free
#define AS_STRIDE 136     // padded smem row stride for A tiles
#define WH_WORDS (512 * WH_STRIDE)
#define REC_SMEM_BYTES ((WH_WORDS + 2 * 32 * AS_STRIDE) * 4)

__global__ __launch_bounds__(256)
void lstm_rec(RecP p)
{
    extern __shared__ unsigned sm[];
    unsigned (*Wh_s)[WH_STRIDE] = (unsigned(*)[WH_STRIDE])sm;
    unsigned (*As)[32][AS_STRIDE] = (unsigned(*)[32][AS_STRIDE])(sm + WH_WORDS);

    const int dir  = blockIdx.y;
    const int j0   = blockIdx.x * 16;
    const int tid  = threadIdx.x;
    const int w    = tid >> 5;
    const int lane = tid & 31;
    const int g    = lane >> 2;
    const int tig  = lane & 3;
    const int mbase = w * 16;

    const float* __restrict__ xp = p.xp[dir];
    const float* __restrict__ Wh = p.Wh[dir];
    float* __restrict__ hb = p.h[dir];
    const long bstride = p.bstride;
    const long tstride = p.tstride;

    // ---- preload Wh gate-gathered tile: 512 k x 64 cols (tf32) ----
    for (int i = tid; i < 512 * 16; i += 256) {
        int k  = i >> 4;
        int c4 = (i & 15) * 4;
        int gate = c4 >> 4;
        int jj   = c4 & 15;
        float4 v = *(const float4*)(Wh + (size_t)k * 2048 + gate * 512 + j0 + jj);
        Wh_s[k][c4 + 0] = f2tf32(v.x);
        Wh_s[k][c4 + 1] = f2tf32(v.y);
        Wh_s[k][c4 + 2] = f2tf32(v.z);
        Wh_s[k][c4 + 3] = f2tf32(v.w);
    }
    __syncthreads();

    float creg[8];
#pragma unroll
    for (int i = 0; i < 8; i++) creg[i] = 0.f;

    volatile unsigned* flagp = (volatile unsigned*)&g_barflag[dir];

    for (int s = 0; s < TT; s++) {
        const int t = dir ? (TT - 1 - s) : s;

        float acc[8][4];
#pragma unroll
        for (int i = 0; i < 8; i++)
#pragma unroll
            for (int q = 0; q < 4; q++) acc[i][q] = 0.f;

        if (s > 0) {
            const int tp = dir ? (t + 1) : (t - 1);
            const float* hp = hb + (size_t)tp * tstride;

            // prologue: chunk 0
#pragma unroll
            for (int i = 0; i < 4; i++) {
                int lin = tid + i * 256;
                int r = lin >> 3, kq = lin & 7;
                float4 v = *(const float4*)(hp + (size_t)r * bstride + kq * 4);
                As[0][kq * 4 + 0][r] = f2tf32(v.x);
                As[0][kq * 4 + 1][r] = f2tf32(v.y);
                As[0][kq * 4 + 2][r] = f2tf32(v.z);
                As[0][kq * 4 + 3][r] = f2tf32(v.w);
            }
            __syncthreads();

            for (int kc = 0; kc < 16; kc++) {
                const int cur = kc & 1;
                float4 pf[4];
                if (kc < 15) {
                    const int kk2 = (kc + 1) * 32;
#pragma unroll
                    for (int i = 0; i < 4; i++) {
                        int lin = tid + i * 256;
                        int r = lin >> 3, kq = lin & 7;
                        pf[i] = *(const float4*)(hp + (size_t)r * bstride + kk2 + kq * 4);
                    }
                }
                const int kkb = kc * 32;
#pragma unroll
                for (int ks = 0; ks < 4; ks++) {
                    const int k0 = ks * 8;
                    unsigned a[4];
                    a[0] = As[cur][k0 + tig][mbase + g];
                    a[1] = As[cur][k0 + tig][mbase + g + 8];
                    a[2] = As[cur][k0 + tig + 4][mbase + g];
                    a[3] = As[cur][k0 + tig + 4][mbase + g + 8];
#pragma unroll
                    for (int nt = 0; nt < 8; nt++) {
                        unsigned b2[2];
                        b2[0] = Wh_s[kkb + k0 + tig][nt * 8 + g];
                        b2[1] = Wh_s[kkb + k0 + tig + 4][nt * 8 + g];
                        mma_tf32(acc[nt], a, b2);
                    }
                }
                if (kc < 15) {
                    const int nxt = cur ^ 1;
#pragma unroll
                    for (int i = 0; i < 4; i++) {
                        int lin = tid + i * 256;
                        int r = lin >> 3, kq = lin & 7;
                        As[nxt][kq * 4 + 0][r] = f2tf32(pf[i].x);
                        As[nxt][kq * 4 + 1][r] = f2tf32(pf[i].y);
                        As[nxt][kq * 4 + 2][r] = f2tf32(pf[i].z);
                        As[nxt][kq * 4 + 3][r] = f2tf32(pf[i].w);
                    }
                }
                __syncthreads();
            }
        }

        // ---- epilogue: gates = acc + xproj[t]; cell update; write h ----
#pragma unroll
        for (int rr = 0; rr < 2; rr++) {
            int b = mbase + g + rr * 8;
            size_t xbase = ((size_t)b * TT + t) * 2048;
#pragma unroll
            for (int cg = 0; cg < 2; cg++) {
#pragma unroll
                for (int pp = 0; pp < 2; pp++) {
                    int q = rr * 2 + pp;
                    int j = j0 + cg * 8 + tig * 2 + pp;
                    float gi = acc[0 + cg][q] + xp[xbase + 0 * 512 + j];
                    float gf = acc[2 + cg][q] + xp[xbase + 1 * 512 + j];
                    float gg = acc[4 + cg][q] + xp[xbase + 2 * 512 + j];
                    float go = acc[6 + cg][q] + xp[xbase + 3 * 512 + j];
                    float i_ = 1.f / (1.f + expf(-gi));
                    float f_ = 1.f / (1.f + expf(-gf));
                    float G_ = tanhf(gg);
                    float o_ = 1.f / (1.f + expf(-go));
                    int ci = rr * 4 + cg * 2 + pp;
                    float cn = f_ * creg[ci] + i_ * G_;
                    creg[ci] = cn;
                    hb[(size_t)b * bstride + (size_t)t * tstride + j] = o_ * tanhf(cn);
                }
            }
        }

        // ---- per-direction grid barrier (32 CTAs), skip after last step ----
        if (s < TT - 1) {
            __threadfence();
            __syncthreads();
            if (tid == 0) {
                unsigned old = *flagp;
                unsigned v = atomicAdd(&g_barcnt[dir], 1);
                if (v == 31) {
                    g_barcnt[dir] = 0;
                    __threadfence();
                    *flagp = old + 1;
                } else {
                    while (*flagp == old) { }
                }
            }
            __syncthreads();
        }
    }
}

// ---------------- host orchestration ----------------------------------------
extern "C" void kernel_launch(void* const* d_in, const int* in_sizes, int n_in,
                              void* d_out, int out_size)
{
    const float* x  = (const float*)d_in[0];   // [128,256,512]
    const float* Wx = (const float*)d_in[1];   // [2,2,512,2048]
    const float* Wh = (const float*)d_in[2];   // [2,2,512,2048]
    const float* bs = (const float*)d_in[3];   // [2,2,2048]
    float* out = (float*)d_out;                // [128,256,1024]

    float *xp_base, *hist_base;
    cudaGetSymbolAddress((void**)&xp_base,   g_xproj);
    cudaGetSymbolAddress((void**)&hist_base, g_hist);

    float* xp[2]   = { xp_base,   xp_base   + (size_t)BB * TT * G4 };
    float* hist[2] = { hist_base, hist_base + (size_t)BB * TT * HH };

    const size_t WSTRIDE = (size_t)HH * G4;
    const dim3 ggrid(16, 256);

    cudaFuncSetAttribute(lstm_rec, cudaFuncAttributeMaxDynamicSharedMemorySize,
                         REC_SMEM_BYTES);

    // ---- layer 0 input projections ----
    for (int d = 0; d < 2; d++)
        gemm_bias_tf32<<<ggrid, 256>>>(x, Wx + (size_t)d * WSTRIDE,
                                       bs + d * G4, xp[d]);

    // ---- layer 0 recurrence (persistent) ----
    {
        RecP p;
        p.xp[0] = xp[0]; p.xp[1] = xp[1];
        p.Wh[0] = Wh;    p.Wh[1] = Wh + WSTRIDE;
        p.h[0]  = hist[0]; p.h[1] = hist[1];
        p.bstride = (long)TT * HH;
        p.tstride = HH;
        lstm_rec<<<dim3(32, 2), 256, REC_SMEM_BYTES>>>(p);
    }

    // ---- layer 1 input projections ----
    for (int d = 0; d < 2; d++)
        gemm_bias_tf32<<<ggrid, 256>>>(hist[d], Wx + (size_t)(2 + d) * WSTRIDE,
                                       bs + (2 + d) * G4, xp[d]);

    // ---- layer 1 recurrence (h lives directly in d_out) ----
    {
        RecP p;
        p.xp[0] = xp[0]; p.xp[1] = xp[1];
        p.Wh[0] = Wh + 2 * WSTRIDE; p.Wh[1] = Wh + 3 * WSTRIDE;
        p.h[0]  = out; p.h[1] = out + 512;
        p.bstride = (long)TT * 1024;
        p.tstride = 1024;
        lstm_rec<<<dim3(32, 2), 256, REC_SMEM_BYTES>>>(p);
    }
}